// round 13
// baseline (speedup 1.0000x reference)
#include <cuda_runtime.h>
#include <cuda_fp16.h>
#include <math.h>

#define BB 2
#define CC 64
#define NPTS 4096
#define MM 256
#define NS 32
#define R2 0.04f

// -------- scratch (device globals; no allocation allowed) --------
struct ZScratch {
    float  G[BB*CC*CC];
    float  sv[BB*CC];
    double stat[48];      // s1[8],ss1[8],s2[8],ss2[8],s3[8],ss3[8]
    int    bar;
    int    bar2;
    int    cnt[BB*NPTS];
};
__device__ ZScratch g_z;

__device__ int     g_idx[BB*NPTS*NS];
__device__ __half2 g_featsh[BB*NPTS*(MM/2)];  // (B, N, M/2) fp16 pairs
__device__ __half2 g_h2[BB*NPTS*(MM/2)];      // (B, N, M/2) fp16 pairs

#define G_S1  (g_z.stat)
#define G_SS1 (g_z.stat + 8)
#define G_S2  (g_z.stat + 16)
#define G_SS2 (g_z.stat + 24)
#define G_S3  (g_z.stat + 32)
#define G_SS3 (g_z.stat + 40)

__device__ __forceinline__ float gelu_f(float v) {
    return 0.5f * v * (1.0f + erff(v * 0.70710678118654752f));
}

// -------- K1: prep = gram+GN1stats (blocks 0-127) || ball query (blocks 128-383) ----
#define PREP_SMEM 50176
__global__ void __launch_bounds__(256, 4) k_prep(const float* __restrict__ x,
                                                 const float* __restrict__ pos,
                                                 const float* __restrict__ w1,
                                                 const float* __restrict__ b1) {
    extern __shared__ char smu[];
    int tid = threadIdx.x;
    int blk = blockIdx.x;
    int warp = tid >> 5, lane = tid & 31;

    if (blk >= 128) {
        // ======== ball query: 32 points, 8 warps x 4 rounds ========
        float* sx = (float*)smu;
        float* sy = sx + NPTS;
        float* sz = sy + NPTS;
        int*   widx = (int*)(smu + 49152);
        int idx = blk - 128;
        int b = idx >> 7, nbase = (idx & 127) * 32;
        const float* pb = pos + b * 3 * NPTS;
        for (int i = tid; i < NPTS; i += 256) {
            sx[i] = pb[i];
            sy[i] = pb[NPTS + i];
            sz[i] = pb[2*NPTS + i];
        }
        __syncthreads();

        int* wl = widx + warp * NS;
        for (int r = 0; r < 4; r++) {
            int n = nbase + warp*4 + r;
            float xn = sx[n], yn = sy[n], zn = sz[n];
            float sqn = xn*xn + yn*yn + zn*zn;
            int cnt = 0, firstm = -1;
            for (int base = 0; base < NPTS && cnt < NS; base += 32) {
                int mq = base + lane;
                float xm = sx[mq], ym = sy[mq], zm = sz[mq];
                float sqm = xm*xm + ym*ym + zm*zm;
                float dot = xn*xm + yn*ym + zn*zm;
                float d = sqn + sqm - 2.0f * dot;
                bool q = !(d > R2);
                unsigned mask = __ballot_sync(0xffffffffu, q);
                if (mask) {
                    if (firstm < 0) firstm = base + __ffs(mask) - 1;
                    int nq = __popc(mask);
                    int slots = NS - cnt;
                    if (q) {
                        int rank = __popc(mask & ((1u << lane) - 1u));
                        if (rank < slots) wl[cnt + rank] = mq;
                    }
                    cnt += (nq < slots) ? nq : slots;
                }
            }
            __syncwarp();
            if (lane >= cnt) wl[lane] = firstm;
            __syncwarp();
            int j = wl[lane];
            g_idx[(b*NPTS + n)*NS + lane] = j;
            atomicAdd(&g_z.cnt[b*NPTS + j], 1);
            __syncwarp();
        }
        return;
    }

    // ======== gram partial: 64-n chunk ========
    {
        float* sA = (float*)smu;          // [c][n] pitch 68
        int b = blk >> 6, n0 = (blk & 63) * 64;
        for (int e = tid; e < 4096; e += 256) {
            int c = e >> 6, nn = e & 63;
            sA[c*68 + nn] = x[(b*CC + c)*NPTS + n0 + nn];
        }
        __syncthreads();

        int tx = tid & 15, ty = tid >> 4;
        float acc[4][4] = {};
#pragma unroll 16
        for (int k = 0; k < 64; k++) {
            float a[4], h[4];
#pragma unroll
            for (int i = 0; i < 4; i++) a[i] = sA[(ty*4 + i)*68 + k];
#pragma unroll
            for (int j = 0; j < 4; j++) h[j] = sA[(tx*4 + j)*68 + k];
#pragma unroll
            for (int i = 0; i < 4; i++)
#pragma unroll
                for (int j = 0; j < 4; j++)
                    acc[i][j] = fmaf(a[i], h[j], acc[i][j]);
        }
        float* Gb = g_z.G + b*CC*CC;
#pragma unroll
        for (int i = 0; i < 4; i++)
#pragma unroll
            for (int j = 0; j < 4; j++)
                atomicAdd(&Gb[(ty*4 + i)*CC + tx*4 + j], acc[i][j]);
        if (tid < CC) {
            float s = 0.f;
#pragma unroll
            for (int nn = 0; nn < 64; nn++) s += sA[tid*68 + nn];
            atomicAdd(&g_z.sv[b*CC + tid], s);
        }
    }

    __syncthreads();
    __threadfence();
    if (tid == 0) atomicAdd(&g_z.bar, 1);
    if (blk >= 8) return;

    if (tid == 0) {
        while (atomicAdd(&g_z.bar, 0) < 128) __nanosleep(128);
    }
    __syncthreads();

    // ======== GN1 stats (blocks 0-7) ========
    {
        float* sG  = (float*)smu;
        float* sw  = (float*)(smu + 16384);
        float* ssv = (float*)(smu + 33024);
        double* sd  = (double*)(smu + 33280);
        double* ssd = (double*)(smu + 33792);
        int bg = blk;
        int sb = bg >> 2, m0 = (bg & 3) * 64;
        for (int e = tid; e < CC*CC; e += 256) sG[e] = __ldcg(&g_z.G[sb*CC*CC + e]);
        for (int e = tid; e < 64*CC; e += 256) sw[(e >> 6)*65 + (e & 63)] = w1[(m0 + (e >> 6))*CC + (e & 63)];
        if (tid < CC) ssv[tid] = __ldcg(&g_z.sv[sb*CC + tid]);
        __syncthreads();

        int mi = tid >> 2, part = tid & 3;
        float q = 0.f, l = 0.f;
        const float* wrow = sw + mi*65;
#pragma unroll
        for (int cc = 0; cc < 16; cc++) {
            int c = part*16 + cc;
            float wc = wrow[c];
            float in0 = 0.f, in1 = 0.f;
#pragma unroll
            for (int c2 = 0; c2 < 64; c2 += 2) {
                in0 = fmaf(wrow[c2],   sG[c*CC + c2],   in0);
                in1 = fmaf(wrow[c2+1], sG[c*CC + c2+1], in1);
            }
            q = fmaf(wc, in0 + in1, q);
            l = fmaf(wc, ssv[c], l);
        }
        q += __shfl_down_sync(0xffffffffu, q, 1);
        q += __shfl_down_sync(0xffffffffu, q, 2);
        l += __shfl_down_sync(0xffffffffu, l, 1);
        l += __shfl_down_sync(0xffffffffu, l, 2);
        if (part == 0) {
            double bb = (double)b1[m0 + mi];
            sd[mi]  = (double)l + 4096.0 * bb;
            ssd[mi] = (double)q + 2.0 * bb * (double)l + 4096.0 * bb * bb;
        }
        __syncthreads();
        for (int s = 32; s > 0; s >>= 1) {
            if (tid < s) { sd[tid] += sd[tid + s]; ssd[tid] += ssd[tid + s]; }
            __syncthreads();
        }
        if (tid == 0) { G_S1[bg] = sd[0]; G_SS1[bg] = ssd[0]; }
    }
}

// -------- K2: GEMM1 (64m x 64n tile, 8m x 4n thread, 128 threads) + GN1 + GELU
//          + fp16 feats + count-weighted GN2 stats --------
__global__ void k_gemm1f(const float* __restrict__ x, const float* __restrict__ w1,
                         const float* __restrict__ b1, const float* __restrict__ g1,
                         const float* __restrict__ be1, const float* __restrict__ wd) {
    __shared__ float sWt[64*68];
    __shared__ float sX[64*64];
    __shared__ float red1[128], red2[128];
    int b = blockIdx.z, m0 = blockIdx.y * 64, n0 = blockIdx.x * 64;
    int tid = threadIdx.x;
    int bg = b*4 + blockIdx.y;

    for (int e = tid; e < 4096; e += 128) {
        int m = e >> 6, c = e & 63;
        sWt[c*68 + m] = w1[(m0 + m)*CC + c];
    }
    for (int e = tid; e < 4096; e += 128) {
        int c = e >> 6, nn = e & 63;
        sX[c*64 + nn] = x[(b*CC + c)*NPTS + n0 + nn];
    }
    __syncthreads();

    int tx = tid & 15, ty = tid >> 4;
    float acc[8][4] = {};
#pragma unroll 8
    for (int k = 0; k < 64; k++) {
        float4 a0 = *(float4*)&sWt[k*68 + ty*8];
        float4 a1 = *(float4*)&sWt[k*68 + ty*8 + 4];
        float4 h4 = *(float4*)&sX[k*64 + tx*4];
        float a[8] = {a0.x, a0.y, a0.z, a0.w, a1.x, a1.y, a1.z, a1.w};
        float h[4] = {h4.x, h4.y, h4.z, h4.w};
#pragma unroll
        for (int i = 0; i < 8; i++)
#pragma unroll
            for (int j = 0; j < 4; j++)
                acc[i][j] = fmaf(a[i], h[j], acc[i][j]);
    }

    double mean = __ldcg(&G_S1[bg]) * (1.0 / (64.0 * 4096.0));
    double var  = __ldcg(&G_SS1[bg]) * (1.0 / (64.0 * 4096.0)) - mean * mean;
    float rs = (float)rsqrt(var + 1e-5);
    float mn = (float)mean;

    float ga[8], bo[8], wm[8];
#pragma unroll
    for (int i = 0; i < 8; i++) {
        int m = m0 + ty*8 + i;
        float bb = b1[m];
        ga[i] = g1[m] * rs;
        bo[i] = be1[m] - (mn - bb) * ga[i];
        wm[i] = wd[m];
    }
    float w[4];
#pragma unroll
    for (int j = 0; j < 4; j++) w[j] = (float)__ldcg(&g_z.cnt[b*NPTS + n0 + tx*4 + j]);

    float lsum = 0.f, lss = 0.f;
#pragma unroll
    for (int j = 0; j < 4; j++) {
        __half2 hv[4];
#pragma unroll
        for (int p = 0; p < 4; p++) {
            float v0 = gelu_f(fmaf(acc[2*p][j],   ga[2*p],   bo[2*p]));
            float v1 = gelu_f(fmaf(acc[2*p+1][j], ga[2*p+1], bo[2*p+1]));
            hv[p] = __floats2half2_rn(v0, v1);
            float a0 = v0 * wm[2*p], a1 = v1 * wm[2*p+1];
            lsum = fmaf(w[j], a0 + a1, lsum);
            lss  = fmaf(w[j], a0*a0 + a1*a1, lss);
        }
        int n = n0 + tx*4 + j;
        __half2* dst = g_featsh + (size_t)(b*NPTS + n)*(MM/2) + (m0 >> 1) + ty*4;
        *(uint4*)dst = *(uint4*)hv;
    }

    red1[tid] = lsum; red2[tid] = lss;
    __syncthreads();
    for (int s = 64; s > 0; s >>= 1) {
        if (tid < s) { red1[tid] += red1[tid + s]; red2[tid] += red2[tid + s]; }
        __syncthreads();
    }
    if (tid == 0) {
        atomicAdd(&G_S2[bg],  (double)red1[0]);
        atomicAdd(&G_SS2[bg], (double)red2[0]);
    }
}

// -------- K3: gather (warp per point, uint4 loads) + GN2 + maxpool + GELU -> h2 fp16 --------
__global__ void k_gather(const float* __restrict__ wd, const float* __restrict__ gd,
                         const float* __restrict__ bed) {
    __shared__ float sA[MM], sBc[MM];
    __shared__ int sI[8*NS];
    int blk = blockIdx.x;
    int b = blk >> 9, n0 = (blk & 511) * 8;
    int tid = threadIdx.x;

    {
        int m = tid;
        int bg = b*4 + (m >> 6);
        double mean = G_S2[bg] * (1.0 / 8388608.0);
        double var  = G_SS2[bg] * (1.0 / 8388608.0) - mean * mean;
        float rsv = (float)rsqrt(var + 1e-5);
        sA[m]  = wd[m] * rsv * gd[m];
        sBc[m] = bed[m] - (float)((double)rsv * mean) * gd[m];
    }
    sI[tid] = g_idx[(b*NPTS + n0)*NS + tid];
    __syncthreads();

    int warp = tid >> 5, lane = tid & 31;
    int n = n0 + warp;
    const int* il = sI + warp * NS;
    const uint4* fb = ((const uint4*)(g_featsh + (size_t)b*NPTS*(MM/2))) + lane;

    __half2 hneg = __half2half2(__float2half(-65504.f));
    __half2 hpos = __half2half2(__float2half( 65504.f));
    __half2 mxA[4] = {hneg, hneg, hneg, hneg};
    __half2 mnA[4] = {hpos, hpos, hpos, hpos};
    __half2 mxB[4] = {hneg, hneg, hneg, hneg};
    __half2 mnB[4] = {hpos, hpos, hpos, hpos};

#pragma unroll
    for (int s = 0; s < NS; s += 2) {
        uint4 va = fb[(size_t)il[s]   * 32];
        uint4 vb = fb[(size_t)il[s+1] * 32];
        const __half2* ha = (const __half2*)&va;
        const __half2* hb = (const __half2*)&vb;
#pragma unroll
        for (int u = 0; u < 4; u++) {
            mxA[u] = __hmax2(mxA[u], ha[u]); mnA[u] = __hmin2(mnA[u], ha[u]);
            mxB[u] = __hmax2(mxB[u], hb[u]); mnB[u] = __hmin2(mnB[u], hb[u]);
        }
    }

    __half2 outv[4];
#pragma unroll
    for (int u = 0; u < 4; u++) {
        float2 fmx = __half22float2(__hmax2(mxA[u], mxB[u]));
        float2 fmn = __half22float2(__hmin2(mnA[u], mnB[u]));
        int ch = 8*lane + 2*u;
        float A0 = sA[ch],   B0 = sBc[ch];
        float A1 = sA[ch+1], B1 = sBc[ch+1];
        float v0 = (A0 >= 0.f) ? fmx.x : fmn.x;
        float v1 = (A1 >= 0.f) ? fmx.y : fmn.y;
        float r0 = gelu_f(fmaf(A0, v0, B0));
        float r1 = gelu_f(fmaf(A1, v1, B1));
        outv[u] = __floats2half2_rn(r0, r1);
    }
    ((uint4*)(g_h2 + (size_t)(b*NPTS + n)*(MM/2)))[lane] = *(uint4*)outv;
}

// -------- K4: GEMM2 split-K, fp16 operands staged ONCE; sRed ALIASES sW2h
//          + GN3 stats + barrier + apply + residual ----
// static smem ~45 KB -> 4 CTAs/SM -> capacity 592 >= 512, barrier safe
union GemmShared {
    __half w2h[256*68];     // 34816 B, live during main loop only
    float  red[4*1024];     // 16384 B, live after main loop (aliased, sync-separated)
};
__global__ void __launch_bounds__(256, 4) k_gemm2f(
    const float* __restrict__ w2, const float* __restrict__ b2,
    const float* __restrict__ x,  const float* __restrict__ g2,
    const float* __restrict__ be2, float* __restrict__ out) {
    __shared__ GemmShared u;          // 34816 B
    __shared__ __half sHh[256*20];    // 10240 B
    __shared__ float sacc[4], sss[4];
    __shared__ float sMean[4], sRs[4];

    int blk = blockIdx.x;
    int b = blk >> 8, n0 = (blk & 255) * 16;
    int tid = threadIdx.x;
    if (tid < 4) { sacc[tid] = 0.f; sss[tid] = 0.f; }

    // ---- stage w2 -> fp16 [k][c] (once) ----
    for (int e = tid; e < 4096; e += 256) {
        int c = e >> 6, kq = e & 63;              // kq = k-quad
        float4 v = *(const float4*)&w2[c*MM + kq*4];
        u.w2h[(4*kq + 0)*68 + c] = __float2half_rn(v.x);
        u.w2h[(4*kq + 1)*68 + c] = __float2half_rn(v.y);
        u.w2h[(4*kq + 2)*68 + c] = __float2half_rn(v.z);
        u.w2h[(4*kq + 3)*68 + c] = __float2half_rn(v.w);
    }
    // ---- stage h2 -> fp16 [k][n] (once) ----
    for (int e = tid; e < 512; e += 256) {
        int n = e >> 5, ko = e & 31;              // ko = k-octet
        uint4 raw = *(const uint4*)&g_h2[(size_t)(b*NPTS + n0 + n)*(MM/2) + ko*4];
        const __half* hp = (const __half*)&raw;
#pragma unroll
        for (int i = 0; i < 8; i++)
            sHh[(8*ko + i)*20 + n] = hp[i];
    }
    __syncthreads();

    int kg = tid >> 6;             // k-group 0..3 (64 k each)
    int t  = tid & 63;
    int cq = t >> 2, nq = t & 3;   // c-quad 0..15, n-quad 0..3

    float acc[4][4] = {};
    int k0 = kg * 64;
#pragma unroll 8
    for (int kk = 0; kk < 64; kk++) {
        int k = k0 + kk;
        __half2 aw0 = *(const __half2*)&u.w2h[k*68 + cq*4];
        __half2 aw1 = *(const __half2*)&u.w2h[k*68 + cq*4 + 2];
        __half2 hw0 = *(const __half2*)&sHh[k*20 + nq*4];
        __half2 hw1 = *(const __half2*)&sHh[k*20 + nq*4 + 2];
        float2 af0 = __half22float2(aw0), af1 = __half22float2(aw1);
        float2 hf0 = __half22float2(hw0), hf1 = __half22float2(hw1);
        float a[4] = {af0.x, af0.y, af1.x, af1.y};
        float h[4] = {hf0.x, hf0.y, hf1.x, hf1.y};
#pragma unroll
        for (int i = 0; i < 4; i++)
#pragma unroll
            for (int j = 0; j < 4; j++)
                acc[i][j] = fmaf(a[i], h[j], acc[i][j]);
    }

    // reduce across the 4 k-groups via smem (sRed aliases dead w2h region)
    __syncthreads();
    float* sRed = u.red;
#pragma unroll
    for (int i = 0; i < 4; i++)
#pragma unroll
        for (int j = 0; j < 4; j++) {
            int p = (cq*4 + i)*16 + (nq*4 + j);    // c*16 + n
            sRed[kg*1024 + p] = acc[i][j];
        }
    __syncthreads();

    float val[4];
    float lsum[4], lss[4];
#pragma unroll
    for (int r = 0; r < 4; r++) {
        int p = tid + r*256;
        float v = sRed[p] + sRed[1024 + p] + sRed[2048 + p] + sRed[3072 + p];
        int c = p >> 4;
        v += b2[c];
        val[r] = v;
        lsum[r] = v;
        lss[r]  = v*v;
    }
#pragma unroll
    for (int r = 0; r < 4; r++) {
#pragma unroll
        for (int o = 16; o > 0; o >>= 1) {
            lsum[r] += __shfl_down_sync(0xffffffffu, lsum[r], o);
            lss[r]  += __shfl_down_sync(0xffffffffu, lss[r],  o);
        }
    }
    if ((tid & 31) == 0) {
#pragma unroll
        for (int r = 0; r < 4; r++) {
            atomicAdd(&sacc[r], lsum[r]);
            atomicAdd(&sss[r],  lss[r]);
        }
    }
    __syncthreads();
    if (tid < 4) {
        atomicAdd(&G_S3[b*4 + tid],  (double)sacc[tid]);
        atomicAdd(&G_SS3[b*4 + tid], (double)sss[tid]);
        __threadfence();
    }
    __syncthreads();

    if (tid == 0) {
        atomicAdd(&g_z.bar2, 1);
        while (atomicAdd(&g_z.bar2, 0) < 512) __nanosleep(128);
    }
    __syncthreads();

    if (tid < 4) {
        double s  = atomicAdd(&G_S3[b*4 + tid],  0.0);
        double ss = atomicAdd(&G_SS3[b*4 + tid], 0.0);
        double mean = s * (1.0 / 65536.0);
        double var  = ss * (1.0 / 65536.0) - mean * mean;
        sMean[tid] = (float)mean;
        sRs[tid]   = (float)rsqrt(var + 1e-5);
    }
    __syncthreads();

#pragma unroll
    for (int r = 0; r < 4; r++) {
        int p = tid + r*256;
        int c = p >> 4, n = p & 15;
        float ga = sRs[r] * g2[c];
        float bo = be2[c] - sMean[r] * ga;
        size_t off = (size_t)(b*CC + c)*NPTS + n0 + n;
        out[off] = fmaf(val[r], ga, bo) + x[off];
    }
}

extern "C" void kernel_launch(void* const* d_in, const int* in_sizes, int n_in,
                              void* d_out, int out_size) {
    const float* x   = (const float*)d_in[0];
    const float* pos = (const float*)d_in[1];
    const float* w1  = (const float*)d_in[2];
    const float* b1  = (const float*)d_in[3];
    const float* g1  = (const float*)d_in[4];
    const float* be1 = (const float*)d_in[5];
    const float* wd  = (const float*)d_in[6];
    const float* gd  = (const float*)d_in[7];
    const float* bed = (const float*)d_in[8];
    const float* w2  = (const float*)d_in[9];
    const float* b2  = (const float*)d_in[10];
    const float* g2  = (const float*)d_in[11];
    const float* be2 = (const float*)d_in[12];
    float* out = (float*)d_out;

    static int inited = 0;
    if (!inited) {
        cudaFuncSetAttribute(k_prep, cudaFuncAttributeMaxDynamicSharedMemorySize, PREP_SMEM);
        inited = 1;
    }

    void* p_z;
    cudaGetSymbolAddress(&p_z, g_z);
    cudaMemsetAsync(p_z, 0, sizeof(ZScratch));

    k_prep  <<<384, 256, PREP_SMEM>>>(x, pos, w1, b1);
    k_gemm1f<<<dim3(NPTS/64, MM/64, BB), 128>>>(x, w1, b1, g1, be1, wd);
    k_gather<<<BB*NPTS/8, 256>>>(wd, gd, bed);
    k_gemm2f<<<512, 256>>>(w2, b2, x, g2, be2, out);
}

// round 14
// speedup vs baseline: 1.0829x; 1.0829x over previous
#include <cuda_runtime.h>
#include <cuda_fp16.h>
#include <math.h>

#define BB 2
#define CC 64
#define NPTS 4096
#define MM 256
#define NS 32
#define R2 0.04f

// -------- scratch (device globals; no allocation allowed) --------
struct ZScratch {
    float  G[BB*CC*CC];
    float  sv[BB*CC];
    double stat[48];      // s1[8],ss1[8],s2[8],ss2[8],s3[8],ss3[8]
    int    bar;
    int    bar2;
    int    cnt[BB*NPTS];
};
__device__ ZScratch g_z;

__device__ int     g_idx[BB*NPTS*NS];
__device__ __half2 g_featsh[BB*NPTS*(MM/2)];  // (B, N, M/2) fp16 pairs
__device__ __half2 g_h2[BB*NPTS*(MM/2)];      // (B, N, M/2) fp16 pairs

#define G_S1  (g_z.stat)
#define G_SS1 (g_z.stat + 8)
#define G_S2  (g_z.stat + 16)
#define G_SS2 (g_z.stat + 24)
#define G_S3  (g_z.stat + 32)
#define G_SS3 (g_z.stat + 40)

__device__ __forceinline__ float gelu_f(float v) {
    return 0.5f * v * (1.0f + erff(v * 0.70710678118654752f));
}

// -------- K1: prep = gram+GN1stats (blocks 0-127) || ball query (blocks 128-383) ----
#define PREP_SMEM 50176
__global__ void __launch_bounds__(256, 4) k_prep(const float* __restrict__ x,
                                                 const float* __restrict__ pos,
                                                 const float* __restrict__ w1,
                                                 const float* __restrict__ b1) {
    extern __shared__ char smu[];
    int tid = threadIdx.x;
    int blk = blockIdx.x;
    int warp = tid >> 5, lane = tid & 31;

    if (blk >= 128) {
        // ======== ball query: 32 points, 8 warps x 4 rounds ========
        float* sx = (float*)smu;
        float* sy = sx + NPTS;
        float* sz = sy + NPTS;
        int*   widx = (int*)(smu + 49152);
        int idx = blk - 128;
        int b = idx >> 7, nbase = (idx & 127) * 32;
        const float* pb = pos + b * 3 * NPTS;
        for (int i = tid; i < NPTS; i += 256) {
            sx[i] = pb[i];
            sy[i] = pb[NPTS + i];
            sz[i] = pb[2*NPTS + i];
        }
        __syncthreads();

        int* wl = widx + warp * NS;
        for (int r = 0; r < 4; r++) {
            int n = nbase + warp*4 + r;
            float xn = sx[n], yn = sy[n], zn = sz[n];
            float sqn = xn*xn + yn*yn + zn*zn;
            int cnt = 0, firstm = -1;
            for (int base = 0; base < NPTS && cnt < NS; base += 32) {
                int mq = base + lane;
                float xm = sx[mq], ym = sy[mq], zm = sz[mq];
                float sqm = xm*xm + ym*ym + zm*zm;
                float dot = xn*xm + yn*ym + zn*zm;
                float d = sqn + sqm - 2.0f * dot;
                bool q = !(d > R2);
                unsigned mask = __ballot_sync(0xffffffffu, q);
                if (mask) {
                    if (firstm < 0) firstm = base + __ffs(mask) - 1;
                    int nq = __popc(mask);
                    int slots = NS - cnt;
                    if (q) {
                        int rank = __popc(mask & ((1u << lane) - 1u));
                        if (rank < slots) wl[cnt + rank] = mq;
                    }
                    cnt += (nq < slots) ? nq : slots;
                }
            }
            __syncwarp();
            if (lane >= cnt) wl[lane] = firstm;
            __syncwarp();
            int j = wl[lane];
            g_idx[(b*NPTS + n)*NS + lane] = j;
            atomicAdd(&g_z.cnt[b*NPTS + j], 1);
            __syncwarp();
        }
        return;
    }

    // ======== gram partial: 64-n chunk ========
    {
        float* sA = (float*)smu;          // [c][n] pitch 68
        int b = blk >> 6, n0 = (blk & 63) * 64;
        for (int e = tid; e < 4096; e += 256) {
            int c = e >> 6, nn = e & 63;
            sA[c*68 + nn] = x[(b*CC + c)*NPTS + n0 + nn];
        }
        __syncthreads();

        int tx = tid & 15, ty = tid >> 4;
        float acc[4][4] = {};
#pragma unroll 16
        for (int k = 0; k < 64; k++) {
            float a[4], h[4];
#pragma unroll
            for (int i = 0; i < 4; i++) a[i] = sA[(ty*4 + i)*68 + k];
#pragma unroll
            for (int j = 0; j < 4; j++) h[j] = sA[(tx*4 + j)*68 + k];
#pragma unroll
            for (int i = 0; i < 4; i++)
#pragma unroll
                for (int j = 0; j < 4; j++)
                    acc[i][j] = fmaf(a[i], h[j], acc[i][j]);
        }
        float* Gb = g_z.G + b*CC*CC;
#pragma unroll
        for (int i = 0; i < 4; i++)
#pragma unroll
            for (int j = 0; j < 4; j++)
                atomicAdd(&Gb[(ty*4 + i)*CC + tx*4 + j], acc[i][j]);
        if (tid < CC) {
            float s = 0.f;
#pragma unroll
            for (int nn = 0; nn < 64; nn++) s += sA[tid*68 + nn];
            atomicAdd(&g_z.sv[b*CC + tid], s);
        }
    }

    __syncthreads();
    __threadfence();
    if (tid == 0) atomicAdd(&g_z.bar, 1);
    if (blk >= 8) return;

    if (tid == 0) {
        while (atomicAdd(&g_z.bar, 0) < 128) __nanosleep(128);
    }
    __syncthreads();

    // ======== GN1 stats (blocks 0-7) ========
    {
        float* sG  = (float*)smu;
        float* sw  = (float*)(smu + 16384);
        float* ssv = (float*)(smu + 33024);
        double* sd  = (double*)(smu + 33280);
        double* ssd = (double*)(smu + 33792);
        int bg = blk;
        int sb = bg >> 2, m0 = (bg & 3) * 64;
        for (int e = tid; e < CC*CC; e += 256) sG[e] = __ldcg(&g_z.G[sb*CC*CC + e]);
        for (int e = tid; e < 64*CC; e += 256) sw[(e >> 6)*65 + (e & 63)] = w1[(m0 + (e >> 6))*CC + (e & 63)];
        if (tid < CC) ssv[tid] = __ldcg(&g_z.sv[sb*CC + tid]);
        __syncthreads();

        int mi = tid >> 2, part = tid & 3;
        float q = 0.f, l = 0.f;
        const float* wrow = sw + mi*65;
#pragma unroll
        for (int cc = 0; cc < 16; cc++) {
            int c = part*16 + cc;
            float wc = wrow[c];
            float in0 = 0.f, in1 = 0.f;
#pragma unroll
            for (int c2 = 0; c2 < 64; c2 += 2) {
                in0 = fmaf(wrow[c2],   sG[c*CC + c2],   in0);
                in1 = fmaf(wrow[c2+1], sG[c*CC + c2+1], in1);
            }
            q = fmaf(wc, in0 + in1, q);
            l = fmaf(wc, ssv[c], l);
        }
        q += __shfl_down_sync(0xffffffffu, q, 1);
        q += __shfl_down_sync(0xffffffffu, q, 2);
        l += __shfl_down_sync(0xffffffffu, l, 1);
        l += __shfl_down_sync(0xffffffffu, l, 2);
        if (part == 0) {
            double bb = (double)b1[m0 + mi];
            sd[mi]  = (double)l + 4096.0 * bb;
            ssd[mi] = (double)q + 2.0 * bb * (double)l + 4096.0 * bb * bb;
        }
        __syncthreads();
        for (int s = 32; s > 0; s >>= 1) {
            if (tid < s) { sd[tid] += sd[tid + s]; ssd[tid] += ssd[tid + s]; }
            __syncthreads();
        }
        if (tid == 0) { G_S1[bg] = sd[0]; G_SS1[bg] = ssd[0]; }
    }
}

// -------- K2: GEMM1 (64m x 64n tile, 8m x 4n thread, 128 threads) + GN1 + GELU
//          + fp16 feats + count-weighted GN2 stats --------
__global__ void k_gemm1f(const float* __restrict__ x, const float* __restrict__ w1,
                         const float* __restrict__ b1, const float* __restrict__ g1,
                         const float* __restrict__ be1, const float* __restrict__ wd) {
    __shared__ float sWt[64*68];
    __shared__ float sX[64*64];
    __shared__ float red1[128], red2[128];
    int b = blockIdx.z, m0 = blockIdx.y * 64, n0 = blockIdx.x * 64;
    int tid = threadIdx.x;
    int bg = b*4 + blockIdx.y;

    for (int e = tid; e < 4096; e += 128) {
        int m = e >> 6, c = e & 63;
        sWt[c*68 + m] = w1[(m0 + m)*CC + c];
    }
    for (int e = tid; e < 4096; e += 128) {
        int c = e >> 6, nn = e & 63;
        sX[c*64 + nn] = x[(b*CC + c)*NPTS + n0 + nn];
    }
    __syncthreads();

    int tx = tid & 15, ty = tid >> 4;
    float acc[8][4] = {};
#pragma unroll 8
    for (int k = 0; k < 64; k++) {
        float4 a0 = *(float4*)&sWt[k*68 + ty*8];
        float4 a1 = *(float4*)&sWt[k*68 + ty*8 + 4];
        float4 h4 = *(float4*)&sX[k*64 + tx*4];
        float a[8] = {a0.x, a0.y, a0.z, a0.w, a1.x, a1.y, a1.z, a1.w};
        float h[4] = {h4.x, h4.y, h4.z, h4.w};
#pragma unroll
        for (int i = 0; i < 8; i++)
#pragma unroll
            for (int j = 0; j < 4; j++)
                acc[i][j] = fmaf(a[i], h[j], acc[i][j]);
    }

    double mean = __ldcg(&G_S1[bg]) * (1.0 / (64.0 * 4096.0));
    double var  = __ldcg(&G_SS1[bg]) * (1.0 / (64.0 * 4096.0)) - mean * mean;
    float rs = (float)rsqrt(var + 1e-5);
    float mn = (float)mean;

    float ga[8], bo[8], wm[8];
#pragma unroll
    for (int i = 0; i < 8; i++) {
        int m = m0 + ty*8 + i;
        float bb = b1[m];
        ga[i] = g1[m] * rs;
        bo[i] = be1[m] - (mn - bb) * ga[i];
        wm[i] = wd[m];
    }
    float w[4];
#pragma unroll
    for (int j = 0; j < 4; j++) w[j] = (float)__ldcg(&g_z.cnt[b*NPTS + n0 + tx*4 + j]);

    float lsum = 0.f, lss = 0.f;
#pragma unroll
    for (int j = 0; j < 4; j++) {
        __half2 hv[4];
#pragma unroll
        for (int p = 0; p < 4; p++) {
            float v0 = gelu_f(fmaf(acc[2*p][j],   ga[2*p],   bo[2*p]));
            float v1 = gelu_f(fmaf(acc[2*p+1][j], ga[2*p+1], bo[2*p+1]));
            hv[p] = __floats2half2_rn(v0, v1);
            float a0 = v0 * wm[2*p], a1 = v1 * wm[2*p+1];
            lsum = fmaf(w[j], a0 + a1, lsum);
            lss  = fmaf(w[j], a0*a0 + a1*a1, lss);
        }
        int n = n0 + tx*4 + j;
        __half2* dst = g_featsh + (size_t)(b*NPTS + n)*(MM/2) + (m0 >> 1) + ty*4;
        *(uint4*)dst = *(uint4*)hv;
    }

    red1[tid] = lsum; red2[tid] = lss;
    __syncthreads();
    for (int s = 64; s > 0; s >>= 1) {
        if (tid < s) { red1[tid] += red1[tid + s]; red2[tid] += red2[tid + s]; }
        __syncthreads();
    }
    if (tid == 0) {
        atomicAdd(&G_S2[bg],  (double)red1[0]);
        atomicAdd(&G_SS2[bg], (double)red2[0]);
    }
}

// -------- K3: gather (warp per point, uint4 loads) + GN2 + maxpool + GELU -> h2 fp16 --------
__global__ void k_gather(const float* __restrict__ wd, const float* __restrict__ gd,
                         const float* __restrict__ bed) {
    __shared__ float sA[MM], sBc[MM];
    __shared__ int sI[8*NS];
    int blk = blockIdx.x;
    int b = blk >> 9, n0 = (blk & 511) * 8;
    int tid = threadIdx.x;

    {
        int m = tid;
        int bg = b*4 + (m >> 6);
        double mean = G_S2[bg] * (1.0 / 8388608.0);
        double var  = G_SS2[bg] * (1.0 / 8388608.0) - mean * mean;
        float rsv = (float)rsqrt(var + 1e-5);
        sA[m]  = wd[m] * rsv * gd[m];
        sBc[m] = bed[m] - (float)((double)rsv * mean) * gd[m];
    }
    sI[tid] = g_idx[(b*NPTS + n0)*NS + tid];
    __syncthreads();

    int warp = tid >> 5, lane = tid & 31;
    int n = n0 + warp;
    const int* il = sI + warp * NS;
    const uint4* fb = ((const uint4*)(g_featsh + (size_t)b*NPTS*(MM/2))) + lane;

    __half2 hneg = __half2half2(__float2half(-65504.f));
    __half2 hpos = __half2half2(__float2half( 65504.f));
    __half2 mxA[4] = {hneg, hneg, hneg, hneg};
    __half2 mnA[4] = {hpos, hpos, hpos, hpos};
    __half2 mxB[4] = {hneg, hneg, hneg, hneg};
    __half2 mnB[4] = {hpos, hpos, hpos, hpos};

#pragma unroll
    for (int s = 0; s < NS; s += 2) {
        uint4 va = fb[(size_t)il[s]   * 32];
        uint4 vb = fb[(size_t)il[s+1] * 32];
        const __half2* ha = (const __half2*)&va;
        const __half2* hb = (const __half2*)&vb;
#pragma unroll
        for (int u = 0; u < 4; u++) {
            mxA[u] = __hmax2(mxA[u], ha[u]); mnA[u] = __hmin2(mnA[u], ha[u]);
            mxB[u] = __hmax2(mxB[u], hb[u]); mnB[u] = __hmin2(mnB[u], hb[u]);
        }
    }

    __half2 outv[4];
#pragma unroll
    for (int u = 0; u < 4; u++) {
        float2 fmx = __half22float2(__hmax2(mxA[u], mxB[u]));
        float2 fmn = __half22float2(__hmin2(mnA[u], mnB[u]));
        int ch = 8*lane + 2*u;
        float A0 = sA[ch],   B0 = sBc[ch];
        float A1 = sA[ch+1], B1 = sBc[ch+1];
        float v0 = (A0 >= 0.f) ? fmx.x : fmn.x;
        float v1 = (A1 >= 0.f) ? fmx.y : fmn.y;
        float r0 = gelu_f(fmaf(A0, v0, B0));
        float r1 = gelu_f(fmaf(A1, v1, B1));
        outv[u] = __floats2half2_rn(r0, r1);
    }
    ((uint4*)(g_h2 + (size_t)(b*NPTS + n)*(MM/2)))[lane] = *(uint4*)outv;
}

// -------- K4: GEMM2 single-stage split-K (64c x 32n, 2 k-groups, 4c x 4n thread)
//          + GN3 stats + barrier + apply + residual ----
// grid 256, block 256, dyn smem 102400 B -> 2 CTAs/SM -> capacity 296 >= 256, barrier safe
#define G2_SMEM 102400
__global__ void __launch_bounds__(256, 2) k_gemm2f(
    const float* __restrict__ w2, const float* __restrict__ b2,
    const float* __restrict__ x,  const float* __restrict__ g2,
    const float* __restrict__ be2, float* __restrict__ out) {
    extern __shared__ float smf[];
    float* sW2t = smf;            // [k][64] swizzled: 65536 B; reused as sRed after loop
    float* sH   = smf + 16384;    // [k][36]: 36864 B
    __shared__ float sacc[4], sss[4];
    __shared__ float sMean[4], sRs[4];

    int blk = blockIdx.x;
    int b = blk >> 7, n0 = (blk & 127) * 32;
    int tid = threadIdx.x;
    if (tid < 4) { sacc[tid] = 0.f; sss[tid] = 0.f; }

    // ---- stage w2 -> [k][c] swizzled (once) ----
    for (int e = tid; e < 4096; e += 256) {
        int c = e >> 6, kq = e & 63;
        float4 v = *(const float4*)&w2[c*MM + kq*4];
        float vv[4] = {v.x, v.y, v.z, v.w};
#pragma unroll
        for (int i = 0; i < 4; i++) {
            int k = 4*kq + i;
            sW2t[k*64 + (c ^ (((k >> 3) & 7) << 2))] = vv[i];
        }
    }
    // ---- stage h2 fp16 -> sH fp32 [k][n] pitch 36 (once) ----
    for (int e = tid; e < 4096; e += 256) {
        int n = e >> 7, mp = e & 127;
        float2 v = __half22float2(g_h2[(size_t)(b*NPTS + n0 + n)*(MM/2) + mp]);
        sH[(2*mp)*36 + n]     = v.x;
        sH[(2*mp + 1)*36 + n] = v.y;
    }
    __syncthreads();

    int kg = tid >> 7;             // k-group 0..1 (128 k each)
    int t  = tid & 127;
    int cq = t >> 3, nq = t & 7;   // c-quad 0..15, n-quad 0..7

    float acc[4][4] = {};
    int k0 = kg * 128;
#pragma unroll 8
    for (int kk = 0; kk < 128; kk++) {
        int k = k0 + kk;
        float4 a4 = *(float4*)&sW2t[k*64 + ((cq << 2) ^ (((k >> 3) & 7) << 2))];
        float4 h4 = *(float4*)&sH[k*36 + (nq << 2)];
        float a[4] = {a4.x, a4.y, a4.z, a4.w};
        float h[4] = {h4.x, h4.y, h4.z, h4.w};
#pragma unroll
        for (int i = 0; i < 4; i++)
#pragma unroll
            for (int j = 0; j < 4; j++)
                acc[i][j] = fmaf(a[i], h[j], acc[i][j]);
    }

    // reduce across the 2 k-groups via smem (sRed aliases dead sW2t)
    __syncthreads();
    float* sRed = sW2t;
#pragma unroll
    for (int i = 0; i < 4; i++)
#pragma unroll
        for (int j = 0; j < 4; j++) {
            int p = (cq*4 + i)*32 + (nq*4 + j);    // c*32 + n
            sRed[kg*2048 + p] = acc[i][j];
        }
    __syncthreads();

    // thread handles p = tid + r*256, r=0..7 ; GN3 group of r is r>>1
    float val[8];
    float lsum[4] = {0.f,0.f,0.f,0.f}, lss[4] = {0.f,0.f,0.f,0.f};
#pragma unroll
    for (int r = 0; r < 8; r++) {
        int p = tid + r*256;
        float v = sRed[p] + sRed[2048 + p];
        int c = p >> 5;
        v += b2[c];
        val[r] = v;
        lsum[r >> 1] += v;
        lss[r >> 1]  += v*v;
    }
#pragma unroll
    for (int g = 0; g < 4; g++) {
#pragma unroll
        for (int o = 16; o > 0; o >>= 1) {
            lsum[g] += __shfl_down_sync(0xffffffffu, lsum[g], o);
            lss[g]  += __shfl_down_sync(0xffffffffu, lss[g],  o);
        }
    }
    if ((tid & 31) == 0) {
#pragma unroll
        for (int g = 0; g < 4; g++) {
            atomicAdd(&sacc[g], lsum[g]);
            atomicAdd(&sss[g],  lss[g]);
        }
    }
    __syncthreads();
    if (tid < 4) {
        atomicAdd(&G_S3[b*4 + tid],  (double)sacc[tid]);
        atomicAdd(&G_SS3[b*4 + tid], (double)sss[tid]);
        __threadfence();
    }
    __syncthreads();

    if (tid == 0) {
        atomicAdd(&g_z.bar2, 1);
        while (atomicAdd(&g_z.bar2, 0) < 256) __nanosleep(128);
    }
    __syncthreads();

    if (tid < 4) {
        double s  = atomicAdd(&G_S3[b*4 + tid],  0.0);
        double ss = atomicAdd(&G_SS3[b*4 + tid], 0.0);
        double mean = s * (1.0 / 65536.0);
        double var  = ss * (1.0 / 65536.0) - mean * mean;
        sMean[tid] = (float)mean;
        sRs[tid]   = (float)rsqrt(var + 1e-5);
    }
    __syncthreads();

#pragma unroll
    for (int r = 0; r < 8; r++) {
        int p = tid + r*256;
        int c = p >> 5, n = p & 31;
        int g = r >> 1;
        float ga = sRs[g] * g2[c];
        float bo = be2[c] - sMean[g] * ga;
        size_t off = (size_t)(b*CC + c)*NPTS + n0 + n;
        out[off] = fmaf(val[r], ga, bo) + x[off];
    }
}

extern "C" void kernel_launch(void* const* d_in, const int* in_sizes, int n_in,
                              void* d_out, int out_size) {
    const float* x   = (const float*)d_in[0];
    const float* pos = (const float*)d_in[1];
    const float* w1  = (const float*)d_in[2];
    const float* b1  = (const float*)d_in[3];
    const float* g1  = (const float*)d_in[4];
    const float* be1 = (const float*)d_in[5];
    const float* wd  = (const float*)d_in[6];
    const float* gd  = (const float*)d_in[7];
    const float* bed = (const float*)d_in[8];
    const float* w2  = (const float*)d_in[9];
    const float* b2  = (const float*)d_in[10];
    const float* g2  = (const float*)d_in[11];
    const float* be2 = (const float*)d_in[12];
    float* out = (float*)d_out;

    static int inited = 0;
    if (!inited) {
        cudaFuncSetAttribute(k_prep,   cudaFuncAttributeMaxDynamicSharedMemorySize, PREP_SMEM);
        cudaFuncSetAttribute(k_gemm2f, cudaFuncAttributeMaxDynamicSharedMemorySize, G2_SMEM);
        inited = 1;
    }

    void* p_z;
    cudaGetSymbolAddress(&p_z, g_z);
    cudaMemsetAsync(p_z, 0, sizeof(ZScratch));

    k_prep  <<<384, 256, PREP_SMEM>>>(x, pos, w1, b1);
    k_gemm1f<<<dim3(NPTS/64, MM/64, BB), 128>>>(x, w1, b1, g1, be1, wd);
    k_gather<<<BB*NPTS/8, 256>>>(wd, gd, bed);
    k_gemm2f<<<256, 256, G2_SMEM>>>(w2, b2, x, g2, be2, out);
}